// round 12
// baseline (speedup 1.0000x reference)
#include <cuda_runtime.h>
#include <cuda_bf16.h>
#include <cstdint>

// ---------------------------------------------------------------------------
// FuseBlock: B=2, C=128, H=W=256.  (b,c,h,w), HW=65536.
// Single-term bf16 mma.sync GEMMs; intermediates bf16; residuals fp32.
// attn: dwconv(q,k) + 8x8 circular conv fused in one kernel.
// K1: LN1 stats fused into staging.  One fold kernel.
// ---------------------------------------------------------------------------

#define EPSV   1e-6f

__device__ float g_bufA[100663296];   // bf16 views too
__device__ float g_bufB[100663296];
__device__ float g_misc[2097152];

#define OFF_M2   262144
#define OFF_R2   393216
#define OFF_M3   524288
#define OFF_R3   655360
#define OFF_S1   786432
#define OFF_T1   787200
#define OFF_S2   787968
#define OFF_T2   788224
#define OFF_WBF  789504

// bf16-element offsets inside WBF region
#define WO_W1HI  0
#define WO_P1HI  98304
#define WO_W2HI  131072
#define WO_P2HI  163840

#define OFF_X1   50331648     // fp32 offset in bufA for x1 (after hidden)
#define ATT_OFF  33554432     // bf16 offset in bufB for attn (after v')
#define OFF_G16  50331648     // bf16 offset in bufB for g

// ---------------------------------------------------------------------------
__device__ __forceinline__ void mma16816(float* d, const uint32_t* a, const uint32_t* b) {
    asm volatile(
        "mma.sync.aligned.m16n8k16.row.col.f32.bf16.bf16.f32 "
        "{%0,%1,%2,%3}, {%4,%5,%6,%7}, {%8,%9}, {%0,%1,%2,%3};"
        : "+f"(d[0]), "+f"(d[1]), "+f"(d[2]), "+f"(d[3])
        : "r"(a[0]), "r"(a[1]), "r"(a[2]), "r"(a[3]), "r"(b[0]), "r"(b[1]));
}

__device__ __forceinline__ uint32_t pack_f2(float a, float b) {
    __nv_bfloat16 ha = __float2bfloat16(a);
    __nv_bfloat16 hb = __float2bfloat16(b);
    return (uint32_t)__bfloat16_as_ushort(ha) | ((uint32_t)__bfloat16_as_ushort(hb) << 16);
}
__device__ __forceinline__ float2 bf2_f2(uint32_t u) {
    float2 r;
    r.x = __uint_as_float(u << 16);
    r.y = __uint_as_float(u & 0xFFFF0000u);
    return r;
}

// ---------------------------------------------------------------------------
// mma GEMM: C[mblocks*128 out-ch, 128 pix @ n0] = A[m,K] @ B[K, pix]
// MODE 1: B fp32 planar; out bf16 = colRstd*(acc - colMean*rowS) + rowT
//         colMean==nullptr -> per-pixel stats computed in-kernel from B.
// MODE 2: B bf16 planar; out fp32 = Xres + acc*scaleRow
// MODE 3: B = v*LN2(attn) (both bf16, 256ch layouts); out fp32; fused stats.
// smem: BsHi word[64 kpair][136 pix] + stats workspace
// ---------------------------------------------------------------------------
#define BROW 136
#define GEMM_SMEM 44032

template <int MODE>
__global__ __launch_bounds__(256)
void mma_gemm(const __nv_bfloat16* __restrict__ Ahi, const void* __restrict__ Bv,
              void* __restrict__ Cv, int K, int CB, int CO, int mblocks,
              const float* __restrict__ colMean, const float* __restrict__ colRstd,
              const float* __restrict__ rowS, const float* __restrict__ rowT,
              const __nv_bfloat16* __restrict__ vbuf, const float* __restrict__ lnW,
              const float* __restrict__ lnB, const float* __restrict__ Xres,
              const float* __restrict__ scaleRow,
              float* __restrict__ m3out, float* __restrict__ r3out)
{
    extern __shared__ __align__(16) char smem[];
    uint32_t* BsHi = reinterpret_cast<uint32_t*>(smem);
    float* sPart = reinterpret_cast<float*>(smem + 34816);   // [8][128]
    float* qPart = sPart + 1024;                             // [8][128]
    float* smean = qPart + 1024;                             // [128]
    float* srstd = smean + 128;                              // [128]

    const int tid = threadIdx.x;
    const int wid = tid >> 5;
    const int lane = tid & 31;
    const int n0 = blockIdx.x * 128;
    const int bg = n0 >> 16;
    const int hw0 = n0 & 65535;
    const int warp_m = wid & 3;
    const int warp_n = wid >> 2;
    const int g  = lane >> 2;
    const int th = lane & 3;
    const bool fstats = (colMean == nullptr);   // used by MODE 1 only

    const int nchunks = K >> 7;
    float sAc[4] = {0.f, 0.f, 0.f, 0.f}, qAc[4] = {0.f, 0.f, 0.f, 0.f};

    for (int mb = 0; mb < mblocks; mb++) {
        const int m0 = mb * 128;

        float acc[2][8][4];
#pragma unroll
        for (int mt = 0; mt < 2; mt++)
#pragma unroll
            for (int nt = 0; nt < 8; nt++)
#pragma unroll
                for (int r = 0; r < 4; r++) acc[mt][nt][r] = 0.f;

        for (int ch = 0; ch < nchunks; ch++) {
            const int kc = ch << 7;

            if (mb == 0) {
                if (ch) __syncthreads();
#pragma unroll
                for (int it = 0; it < 8; it++) {
                    int idx = tid + it * 256;
                    int kp = idx >> 5;
                    int pg = (idx & 31) * 4;
                    int k0 = kc + kp * 2;
                    uint4 W;
                    if (MODE == 1) {
                        const float* Bf = (const float*)Bv;
                        float4 va = *reinterpret_cast<const float4*>(
                            Bf + (((size_t)(bg * CB + k0))     << 16) + hw0 + pg);
                        float4 vb = *reinterpret_cast<const float4*>(
                            Bf + (((size_t)(bg * CB + k0 + 1)) << 16) + hw0 + pg);
                        if (fstats) {
                            sAc[0] += va.x + vb.x; qAc[0] += va.x * va.x + vb.x * vb.x;
                            sAc[1] += va.y + vb.y; qAc[1] += va.y * va.y + vb.y * vb.y;
                            sAc[2] += va.z + vb.z; qAc[2] += va.z * va.z + vb.z * vb.z;
                            sAc[3] += va.w + vb.w; qAc[3] += va.w * va.w + vb.w * vb.w;
                        }
                        W.x = pack_f2(va.x, vb.x);
                        W.y = pack_f2(va.y, vb.y);
                        W.z = pack_f2(va.z, vb.z);
                        W.w = pack_f2(va.w, vb.w);
                    } else if (MODE == 2) {
                        const __nv_bfloat16* Bb = (const __nv_bfloat16*)Bv;
                        uint2 u = *reinterpret_cast<const uint2*>(
                            Bb + (((size_t)(bg * CB + k0))     << 16) + hw0 + pg);
                        uint2 v = *reinterpret_cast<const uint2*>(
                            Bb + (((size_t)(bg * CB + k0 + 1)) << 16) + hw0 + pg);
                        W.x = __byte_perm(u.x, v.x, 0x5410);
                        W.y = __byte_perm(u.x, v.x, 0x7632);
                        W.z = __byte_perm(u.y, v.y, 0x5410);
                        W.w = __byte_perm(u.y, v.y, 0x7632);
                    } else { // MODE 3
                        const __nv_bfloat16* Ab = (const __nv_bfloat16*)Bv;
                        uint2 ua0 = *reinterpret_cast<const uint2*>(
                            Ab + (((size_t)(bg * 256 + k0))     << 16) + hw0 + pg);
                        uint2 ua1 = *reinterpret_cast<const uint2*>(
                            Ab + (((size_t)(bg * 256 + k0 + 1)) << 16) + hw0 + pg);
                        uint2 uv0 = *reinterpret_cast<const uint2*>(
                            vbuf + (((size_t)(bg * 256 + k0))     << 16) + hw0 + pg);
                        uint2 uv1 = *reinterpret_cast<const uint2*>(
                            vbuf + (((size_t)(bg * 256 + k0 + 1)) << 16) + hw0 + pg);
                        float4 m4 = *reinterpret_cast<const float4*>(colMean + n0 + pg);
                        float4 r4 = *reinterpret_cast<const float4*>(colRstd + n0 + pg);
                        float wc0 = lnW[k0], bc0 = lnB[k0];
                        float wc1 = lnW[k0 + 1], bc1 = lnB[k0 + 1];
                        float2 a0 = bf2_f2(ua0.x), a1 = bf2_f2(ua0.y);
                        float2 c0 = bf2_f2(ua1.x), c1 = bf2_f2(ua1.y);
                        float2 v0 = bf2_f2(uv0.x), v1 = bf2_f2(uv0.y);
                        float2 w0 = bf2_f2(uv1.x), w1 = bf2_f2(uv1.y);
                        float r0a = v0.x * ((a0.x - m4.x) * r4.x * wc0 + bc0);
                        float r0b = v0.y * ((a0.y - m4.y) * r4.y * wc0 + bc0);
                        float r0c = v1.x * ((a1.x - m4.z) * r4.z * wc0 + bc0);
                        float r0d = v1.y * ((a1.y - m4.w) * r4.w * wc0 + bc0);
                        float r1a = w0.x * ((c0.x - m4.x) * r4.x * wc1 + bc1);
                        float r1b = w0.y * ((c0.y - m4.y) * r4.y * wc1 + bc1);
                        float r1c = w1.x * ((c1.x - m4.z) * r4.z * wc1 + bc1);
                        float r1d = w1.y * ((c1.y - m4.w) * r4.w * wc1 + bc1);
                        W.x = pack_f2(r0a, r1a);
                        W.y = pack_f2(r0b, r1b);
                        W.z = pack_f2(r0c, r1c);
                        W.w = pack_f2(r0d, r1d);
                    }
                    *reinterpret_cast<uint4*>(BsHi + kp * BROW + pg) = W;
                }
                if (MODE == 1 && fstats) {
                    int tg = tid >> 5, pg4 = (tid & 31) * 4;
                    *reinterpret_cast<float4*>(&sPart[tg * 128 + pg4]) =
                        make_float4(sAc[0], sAc[1], sAc[2], sAc[3]);
                    *reinterpret_cast<float4*>(&qPart[tg * 128 + pg4]) =
                        make_float4(qAc[0], qAc[1], qAc[2], qAc[3]);
                }
                __syncthreads();
                if (MODE == 1 && fstats) {
                    if (tid < 128) {
                        float s = 0.f, q = 0.f;
#pragma unroll
                        for (int tg = 0; tg < 8; tg++) {
                            s += sPart[tg * 128 + tid];
                            q += qPart[tg * 128 + tid];
                        }
                        float m = s * (1.f / 128.f);
                        float var = q * (1.f / 128.f) - m * m;
                        smean[tid] = m;
                        srstd[tid] = rsqrtf(var + EPSV);
                    }
                    __syncthreads();
                }
            }

            // ---- 8 k-steps of 16 ----
#pragma unroll
            for (int ks = 0; ks < 8; ks++) {
                uint32_t ah[2][4];
#pragma unroll
                for (int mt = 0; mt < 2; mt++) {
                    int r = m0 + warp_m * 32 + mt * 16 + g;
                    size_t base = (size_t)r * K + kc + ks * 16 + th * 2;
                    ah[mt][0] = *reinterpret_cast<const uint32_t*>(Ahi + base);
                    ah[mt][1] = *reinterpret_cast<const uint32_t*>(Ahi + base + (size_t)8 * K);
                    ah[mt][2] = *reinterpret_cast<const uint32_t*>(Ahi + base + 8);
                    ah[mt][3] = *reinterpret_cast<const uint32_t*>(Ahi + base + (size_t)8 * K + 8);
                }
                const int kp0 = ks * 8 + th;
                const int kp1 = ks * 8 + 4 + th;
#pragma unroll
                for (int nt = 0; nt < 8; nt++) {
                    int n = warp_n * 64 + nt * 8 + g;
                    uint32_t bh[2];
                    bh[0] = BsHi[kp0 * BROW + n];
                    bh[1] = BsHi[kp1 * BROW + n];
#pragma unroll
                    for (int mt = 0; mt < 2; mt++)
                        mma16816(acc[mt][nt], ah[mt], bh);
                }
            }
        }

        // ---- epilogue ----
        float sEp[16], qEp[16];
        if (MODE == 3) {
#pragma unroll
            for (int i = 0; i < 16; i++) { sEp[i] = 0.f; qEp[i] = 0.f; }
        }
#pragma unroll
        for (int mt = 0; mt < 2; mt++) {
#pragma unroll
            for (int half = 0; half < 2; half++) {
                int o = m0 + warp_m * 32 + mt * 16 + g + half * 8;
                if (MODE == 1) {
                    float sv = rowS[o], tv = rowT[o];
                    __nv_bfloat16* Cb = (__nv_bfloat16*)Cv;
#pragma unroll
                    for (int nt = 0; nt < 8; nt++) {
                        int col = warp_n * 64 + nt * 8 + th * 2;
                        float2 cm, cr;
                        if (fstats) {
                            cm.x = smean[col]; cm.y = smean[col + 1];
                            cr.x = srstd[col]; cr.y = srstd[col + 1];
                        } else {
                            cm = *reinterpret_cast<const float2*>(colMean + n0 + col);
                            cr = *reinterpret_cast<const float2*>(colRstd + n0 + col);
                        }
                        float d0 = cr.x * (acc[mt][nt][half * 2 + 0] - cm.x * sv) + tv;
                        float d1 = cr.y * (acc[mt][nt][half * 2 + 1] - cm.y * sv) + tv;
                        *reinterpret_cast<uint32_t*>(
                            Cb + (((size_t)(bg * CO + o)) << 16) + hw0 + col) = pack_f2(d0, d1);
                    }
                } else {
                    float sc = scaleRow[o];
                    float* Cf = (float*)Cv;
#pragma unroll
                    for (int nt = 0; nt < 8; nt++) {
                        int col = warp_n * 64 + nt * 8 + th * 2;
                        size_t ix = (((size_t)(bg * CO + o)) << 16) + hw0 + col;
                        float2 xr = *reinterpret_cast<const float2*>(Xres + ix);
                        float2 ov;
                        ov.x = xr.x + acc[mt][nt][half * 2 + 0] * sc;
                        ov.y = xr.y + acc[mt][nt][half * 2 + 1] * sc;
                        *reinterpret_cast<float2*>(Cf + ix) = ov;
                        if (MODE == 3) {
                            sEp[nt * 2 + 0] += ov.x;
                            qEp[nt * 2 + 0] += ov.x * ov.x;
                            sEp[nt * 2 + 1] += ov.y;
                            qEp[nt * 2 + 1] += ov.y * ov.y;
                        }
                    }
                }
            }
        }

        if (MODE == 3) {
#pragma unroll
            for (int i = 0; i < 16; i++) {
#pragma unroll
                for (int off = 4; off <= 16; off <<= 1) {
                    sEp[i] += __shfl_xor_sync(0xFFFFFFFFu, sEp[i], off);
                    qEp[i] += __shfl_xor_sync(0xFFFFFFFFu, qEp[i], off);
                }
            }
            __syncthreads();
            float* sP = reinterpret_cast<float*>(smem);
            float* qP = sP + 512;
            if (lane < 4) {
#pragma unroll
                for (int nt = 0; nt < 8; nt++) {
#pragma unroll
                    for (int cc = 0; cc < 2; cc++) {
                        int col = warp_n * 64 + nt * 8 + lane * 2 + cc;
                        sP[warp_m * 128 + col] = sEp[nt * 2 + cc];
                        qP[warp_m * 128 + col] = qEp[nt * 2 + cc];
                    }
                }
            }
            __syncthreads();
            if (tid < 128) {
                float s = sP[tid] + sP[128 + tid] + sP[256 + tid] + sP[384 + tid];
                float q = qP[tid] + qP[128 + tid] + qP[256 + tid] + qP[384 + tid];
                float m = s * (1.f / 128.f);
                float var = q * (1.f / 128.f) - m * m;
                m3out[n0 + tid] = m;
                r3out[n0 + tid] = rsqrtf(var + EPSV);
            }
        }
    }
}

// ---------------------------------------------------------------------------
// bf16-input per-pixel channel stats (for attn LN2)
// ---------------------------------------------------------------------------
__global__ void stats_bf16_kernel(const __nv_bfloat16* __restrict__ in,
                                  float* __restrict__ mean, float* __restrict__ rstd, int C) {
    int p = blockIdx.x * blockDim.x + threadIdx.x;
    int b = p >> 16, hw = p & 65535;
    const __nv_bfloat16* base = in + ((size_t)(b * C) << 16) + hw;
    float s = 0.f, ss = 0.f;
    for (int c = 0; c < C; c += 4) {
        float v0 = __bfloat162float(base[(size_t)(c + 0) << 16]);
        float v1 = __bfloat162float(base[(size_t)(c + 1) << 16]);
        float v2 = __bfloat162float(base[(size_t)(c + 2) << 16]);
        float v3 = __bfloat162float(base[(size_t)(c + 3) << 16]);
        s  += v0 + v1 + v2 + v3;
        ss += v0 * v0 + v1 * v1 + v2 * v2 + v3 * v3;
    }
    float invC = 1.f / (float)C;
    float m = s * invC;
    float var = ss * invC - m * m;
    mean[p] = m;
    rstd[p] = rsqrtf(var + EPSV);
}

// ---------------------------------------------------------------------------
// One fold kernel for all 4 weight matrices. 1280 warp-rows.
// ---------------------------------------------------------------------------
__global__ void fold_all(const float* __restrict__ w_h1, const float* __restrict__ n1w,
                         const float* __restrict__ n1b,
                         const float* __restrict__ w_h2, const float* __restrict__ n3w,
                         const float* __restrict__ n3b, const float* __restrict__ b_h2,
                         const float* __restrict__ w_p1, const float* __restrict__ w_p2,
                         __nv_bfloat16* __restrict__ W1hi, __nv_bfloat16* __restrict__ W2hi,
                         __nv_bfloat16* __restrict__ P1hi, __nv_bfloat16* __restrict__ P2hi,
                         float* __restrict__ s1, float* __restrict__ t1,
                         float* __restrict__ s2, float* __restrict__ t2) {
    int r = blockIdx.x * 8 + (threadIdx.x >> 5);
    int lane = threadIdx.x & 31;
    if (r < 768) {
        float s = 0.f, t = 0.f;
        for (int c = lane; c < 128; c += 32) {
            float wv = w_h1[r * 128 + c];
            float wp = wv * n1w[c];
            W1hi[r * 128 + c] = __float2bfloat16(wp);
            s += wp;
            t += wv * n1b[c];
        }
#pragma unroll
        for (int off = 16; off; off >>= 1) {
            s += __shfl_xor_sync(0xFFFFFFFFu, s, off);
            t += __shfl_xor_sync(0xFFFFFFFFu, t, off);
        }
        if (lane == 0) { s1[r] = s; t1[r] = t; }
    } else if (r < 1024) {
        int o = r - 768;
        float s = 0.f, t = 0.f;
        for (int c = lane; c < 128; c += 32) {
            float wv = w_h2[o * 128 + c];
            float wp = wv * n3w[c];
            W2hi[o * 128 + c] = __float2bfloat16(wp);
            s += wp;
            t += wv * n3b[c];
        }
#pragma unroll
        for (int off = 16; off; off >>= 1) {
            s += __shfl_xor_sync(0xFFFFFFFFu, s, off);
            t += __shfl_xor_sync(0xFFFFFFFFu, t, off);
        }
        if (lane == 0) { s2[o] = s; t2[o] = t + b_h2[o]; }
    } else if (r < 1152) {
        int o = r - 1024;
        for (int c = lane; c < 256; c += 32)
            P1hi[o * 256 + c] = __float2bfloat16(w_p1[o * 256 + c]);
    } else {
        int o = r - 1152;
        for (int c = lane; c < 128; c += 32)
            P2hi[o * 128 + c] = __float2bfloat16(w_p2[o * 128 + c]);
    }
}

// ---------------------------------------------------------------------------
// v-only depthwise 3x3: hidden ch 512..767 -> v' (256-ch layout)
// grid (32 strips, B*256)
// ---------------------------------------------------------------------------
__global__ __launch_bounds__(256)
void dwconv_v(const __nv_bfloat16* __restrict__ hidden, const float* __restrict__ w,
              __nv_bfloat16* __restrict__ vout) {
    int z = blockIdx.y;
    int b = z >> 8, c = z & 255;
    int h0 = blockIdx.x * 8;
    __shared__ float tile[10][258];
    const __nv_bfloat16* base = hidden + ((size_t)(b * 768 + 512 + c) << 16);
    int tid = threadIdx.x;
#pragma unroll
    for (int r = 0; r < 10; r++) {
        int gh = h0 - 1 + r;
        tile[r][tid + 1] = (gh >= 0 && gh < 256) ? __bfloat162float(base[gh * 256 + tid]) : 0.f;
    }
    if (tid < 10) { tile[tid][0] = 0.f; tile[tid][257] = 0.f; }
    __syncthreads();
    const float* wc = w + (size_t)(512 + c) * 9;
    float w0 = wc[0], w1 = wc[1], w2 = wc[2], w3 = wc[3], w4 = wc[4],
          w5 = wc[5], w6 = wc[6], w7 = wc[7], w8 = wc[8];
    __nv_bfloat16* obase = vout + ((size_t)(b * 256 + c) << 16) + h0 * 256 + tid;
#pragma unroll
    for (int y = 0; y < 8; y++) {
        float s = w0 * tile[y][tid]     + w1 * tile[y][tid + 1]     + w2 * tile[y][tid + 2]
                + w3 * tile[y + 1][tid] + w4 * tile[y + 1][tid + 1] + w5 * tile[y + 1][tid + 2]
                + w6 * tile[y + 2][tid] + w7 * tile[y + 2][tid + 1] + w8 * tile[y + 2][tid + 2];
        obase[y * 256] = __float2bfloat16(s);
    }
}

// ---------------------------------------------------------------------------
// Fused: dwconv3(q_c), dwconv3(k_c), 8x8 circular conv per patch -> attn_c
// Block: channel c (0..255) x batch b, strip of 8 rows (= one patch row).
// grid (32, B*256)
// ---------------------------------------------------------------------------
__global__ __launch_bounds__(256)
void attn_fused(const __nv_bfloat16* __restrict__ hidden, const float* __restrict__ wdw,
                __nv_bfloat16* __restrict__ attn) {
    int z = blockIdx.y;
    int b = z >> 8, c = z & 255;
    int h0 = blockIdx.x * 8;
    __shared__ float tq[10][258];
    __shared__ float tk[10][258];
    __shared__ float qs2[32][68];   // [patch][i*8+j]
    __shared__ float ks2[32][68];

    const __nv_bfloat16* qb = hidden + ((size_t)(b * 768 + c)       << 16);
    const __nv_bfloat16* kb = hidden + ((size_t)(b * 768 + 256 + c) << 16);
    int tid = threadIdx.x;
#pragma unroll
    for (int r = 0; r < 10; r++) {
        int gh = h0 - 1 + r;
        bool ok = (gh >= 0 && gh < 256);
        tq[r][tid + 1] = ok ? __bfloat162float(qb[gh * 256 + tid]) : 0.f;
        tk[r][tid + 1] = ok ? __bfloat162float(kb[gh * 256 + tid]) : 0.f;
    }
    if (tid < 10) {
        tq[tid][0] = 0.f; tq[tid][257] = 0.f;
        tk[tid][0] = 0.f; tk[tid][257] = 0.f;
    }
    __syncthreads();

    {
        const float* wq = wdw + (size_t)c * 9;
        const float* wk = wdw + (size_t)(256 + c) * 9;
        float q0 = wq[0], q1 = wq[1], q2 = wq[2], q3 = wq[3], q4 = wq[4],
              q5 = wq[5], q6 = wq[6], q7 = wq[7], q8 = wq[8];
        float k0 = wk[0], k1 = wk[1], k2 = wk[2], k3 = wk[3], k4 = wk[4],
              k5 = wk[5], k6 = wk[6], k7 = wk[7], k8 = wk[8];
        int p = tid >> 3, jj = tid & 7;
#pragma unroll
        for (int y = 0; y < 8; y++) {
            float qv = q0 * tq[y][tid]     + q1 * tq[y][tid + 1]     + q2 * tq[y][tid + 2]
                     + q3 * tq[y + 1][tid] + q4 * tq[y + 1][tid + 1] + q5 * tq[y + 1][tid + 2]
                     + q6 * tq[y + 2][tid] + q7 * tq[y + 2][tid + 1] + q8 * tq[y + 2][tid + 2];
            float kv = k0 * tk[y][tid]     + k1 * tk[y][tid + 1]     + k2 * tk[y][tid + 2]
                     + k3 * tk[y + 1][tid] + k4 * tk[y + 1][tid + 1] + k5 * tk[y + 1][tid + 2]
                     + k6 * tk[y + 2][tid] + k7 * tk[y + 2][tid + 1] + k8 * tk[y + 2][tid + 2];
            qs2[p][y * 8 + jj] = qv;
            ks2[p][y * 8 + jj] = kv;
        }
    }
    __syncthreads();

    // circular conv: warp = row i, lanes = patches
    int i = tid >> 5, p = tid & 31;
    float acc[8];
#pragma unroll
    for (int j = 0; j < 8; j++) acc[j] = 0.f;
#pragma unroll
    for (int a = 0; a < 8; a++) {
        int ra = (i - a) & 7;
        float qr[8], kr[8];
        *reinterpret_cast<float4*>(&qr[0]) = *reinterpret_cast<const float4*>(&qs2[p][a * 8]);
        *reinterpret_cast<float4*>(&qr[4]) = *reinterpret_cast<const float4*>(&qs2[p][a * 8 + 4]);
        *reinterpret_cast<float4*>(&kr[0]) = *reinterpret_cast<const float4*>(&ks2[p][ra * 8]);
        *reinterpret_cast<float4*>(&kr[4]) = *reinterpret_cast<const float4*>(&ks2[p][ra * 8 + 4]);
#pragma unroll
        for (int bq = 0; bq < 8; bq++)
#pragma unroll
            for (int j = 0; j < 8; j++)
                acc[j] += qr[bq] * kr[(j - bq) & 7];
    }

    uint4 ov;
    ov.x = pack_f2(acc[0], acc[1]);
    ov.y = pack_f2(acc[2], acc[3]);
    ov.z = pack_f2(acc[4], acc[5]);
    ov.w = pack_f2(acc[6], acc[7]);
    *reinterpret_cast<uint4*>(attn + ((size_t)(b * 256 + c) << 16)
                              + (h0 + i) * 256 + p * 8) = ov;
}

// ---------------------------------------------------------------------------
// FFN gate (unchanged): dw3x3 on ch c and c+128 of h, multiply. grid (32, B*128)
// ---------------------------------------------------------------------------
__global__ __launch_bounds__(256)
void gate_kernel(const __nv_bfloat16* __restrict__ h, const float* __restrict__ wdw,
                 __nv_bfloat16* __restrict__ g) {
    int z = blockIdx.y;
    int b = z >> 7, c = z & 127;
    int h0 = blockIdx.x * 8;
    __shared__ float t1s[10][258];
    __shared__ float t2s[10][258];
    const __nv_bfloat16* base1 = h + ((size_t)(b * 256 + c) << 16);
    const __nv_bfloat16* base2 = h + ((size_t)(b * 256 + c + 128) << 16);
    int tid = threadIdx.x;
#pragma unroll
    for (int r = 0; r < 10; r++) {
        int gh = h0 - 1 + r;
        bool ok = (gh >= 0 && gh < 256);
        t1s[r][tid + 1] = ok ? __bfloat162float(base1[gh * 256 + tid]) : 0.f;
        t2s[r][tid + 1] = ok ? __bfloat162float(base2[gh * 256 + tid]) : 0.f;
    }
    if (tid < 10) {
        t1s[tid][0] = 0.f; t1s[tid][257] = 0.f;
        t2s[tid][0] = 0.f; t2s[tid][257] = 0.f;
    }
    __syncthreads();
    const float* wa = wdw + (size_t)c * 9;
    const float* wb = wdw + (size_t)(c + 128) * 9;
    float a0 = wa[0], a1 = wa[1], a2 = wa[2], a3 = wa[3], a4 = wa[4],
          a5 = wa[5], a6 = wa[6], a7 = wa[7], a8 = wa[8];
    float b0 = wb[0], b1 = wb[1], b2 = wb[2], b3 = wb[3], b4 = wb[4],
          b5 = wb[5], b6 = wb[6], b7 = wb[7], b8 = wb[8];
    __nv_bfloat16* obase = g + ((size_t)(b * 128 + c) << 16) + h0 * 256 + tid;
#pragma unroll
    for (int y = 0; y < 8; y++) {
        float s1 = a0 * t1s[y][tid]     + a1 * t1s[y][tid + 1]     + a2 * t1s[y][tid + 2]
                 + a3 * t1s[y + 1][tid] + a4 * t1s[y + 1][tid + 1] + a5 * t1s[y + 1][tid + 2]
                 + a6 * t1s[y + 2][tid] + a7 * t1s[y + 2][tid + 1] + a8 * t1s[y + 2][tid + 2];
        float s2 = b0 * t2s[y][tid]     + b1 * t2s[y][tid + 1]     + b2 * t2s[y][tid + 2]
                 + b3 * t2s[y + 1][tid] + b4 * t2s[y + 1][tid + 1] + b5 * t2s[y + 1][tid + 2]
                 + b6 * t2s[y + 2][tid] + b7 * t2s[y + 2][tid + 1] + b8 * t2s[y + 2][tid + 2];
        obase[y * 256] = __float2bfloat16(s1 * s2);
    }
}

// ---------------------------------------------------------------------------
extern "C" void kernel_launch(void* const* d_in, const int* in_sizes, int n_in,
                              void* d_out, int out_size) {
    const float* x      = (const float*)d_in[0];
    const float* n1w    = (const float*)d_in[1];
    const float* n1b    = (const float*)d_in[2];
    const float* w_h1   = (const float*)d_in[3];
    const float* w_dw1  = (const float*)d_in[4];
    const float* n2w    = (const float*)d_in[5];
    const float* n2b    = (const float*)d_in[6];
    const float* w_p1   = (const float*)d_in[7];
    const float* n3w    = (const float*)d_in[8];
    const float* n3b    = (const float*)d_in[9];
    const float* w_h2   = (const float*)d_in[10];
    const float* b_h2   = (const float*)d_in[11];
    const float* w_dw2  = (const float*)d_in[12];
    const float* w_p2   = (const float*)d_in[13];
    const float* scale1 = (const float*)d_in[14];
    const float* scale2 = (const float*)d_in[15];
    float* out = (float*)d_out;

    float *bufA, *bufB, *misc;
    cudaGetSymbolAddress((void**)&bufA, g_bufA);
    cudaGetSymbolAddress((void**)&bufB, g_bufB);
    cudaGetSymbolAddress((void**)&misc, g_misc);

    __nv_bfloat16* bA16 = reinterpret_cast<__nv_bfloat16*>(bufA);
    __nv_bfloat16* bB16 = reinterpret_cast<__nv_bfloat16*>(bufB);

    float* m2 = misc + OFF_M2;
    float* r2 = misc + OFF_R2;
    float* m3 = misc + OFF_M3;
    float* r3 = misc + OFF_R3;
    float* s1 = misc + OFF_S1;
    float* t1 = misc + OFF_T1;
    float* s2 = misc + OFF_S2;
    float* t2 = misc + OFF_T2;
    __nv_bfloat16* wbf = reinterpret_cast<__nv_bfloat16*>(misc + OFF_WBF);
    __nv_bfloat16* W1hi = wbf + WO_W1HI;
    __nv_bfloat16* P1hi = wbf + WO_P1HI;
    __nv_bfloat16* W2hi = wbf + WO_W2HI;
    __nv_bfloat16* P2hi = wbf + WO_P2HI;

    cudaFuncSetAttribute(mma_gemm<1>, cudaFuncAttributeMaxDynamicSharedMemorySize, GEMM_SMEM);
    cudaFuncSetAttribute(mma_gemm<2>, cudaFuncAttributeMaxDynamicSharedMemorySize, GEMM_SMEM);
    cudaFuncSetAttribute(mma_gemm<3>, cudaFuncAttributeMaxDynamicSharedMemorySize, GEMM_SMEM);

    // folds (one kernel)
    fold_all<<<160, 256>>>(w_h1, n1w, n1b, w_h2, n3w, n3b, b_h2, w_p1, w_p2,
                           W1hi, W2hi, P1hi, P2hi, s1, t1, s2, t2);

    // K1: hidden(bf16, 768ch in bufA) = LN1-folded conv1x1(x); stats fused
    mma_gemm<1><<<dim3(1024, 1), 256, GEMM_SMEM>>>(W1hi, x, bA16, 128, 128, 768, 6,
                                                   nullptr, nullptr, s1, t1,
                                                   nullptr, nullptr, nullptr, nullptr, nullptr,
                                                   nullptr, nullptr);
    // v' = dwconv(hidden[512:768]) -> bufB (256-ch layout)
    dwconv_v<<<dim3(32, 512), 256>>>(bA16, w_dw1, bB16);

    // attn = circconv8(dwconv(q), dwconv(k)) -> bufB + ATT_OFF
    attn_fused<<<dim3(32, 512), 256>>>(bA16, w_dw1, bB16 + ATT_OFF);
    stats_bf16_kernel<<<512, 256>>>(bB16 + ATT_OFF, m2, r2, 256);

    // K3b: x1(fp32) = x + scale1 * ( w_p1 @ (v' * LN2(attn)) ); fused stats -> m3,r3
    mma_gemm<3><<<dim3(1024, 1), 256, GEMM_SMEM>>>(P1hi, bB16 + ATT_OFF, bufA + OFF_X1,
                                                   256, 256, 128, 1,
                                                   m2, r2, nullptr, nullptr,
                                                   bB16, n2w, n2b, x, scale1,
                                                   m3, r3);

    // K4: h(bf16, 256ch in bufB) = LN3-folded conv1x1(x1) + b_h2
    mma_gemm<1><<<dim3(1024, 1), 256, GEMM_SMEM>>>(W2hi, bufA + OFF_X1, bB16, 128, 128, 256, 2,
                                                   m3, r3, s2, t2,
                                                   nullptr, nullptr, nullptr, nullptr, nullptr,
                                                   nullptr, nullptr);
    // gate
    gate_kernel<<<dim3(32, 256), 256>>>(bB16, w_dw2, bB16 + OFF_G16);
    // K5b: out = x1 + scale2 * (w_p2 @ g)
    mma_gemm<2><<<dim3(1024, 1), 256, GEMM_SMEM>>>(P2hi, bB16 + OFF_G16, out, 128, 128, 128, 1,
                                                   nullptr, nullptr, nullptr, nullptr,
                                                   nullptr, nullptr, nullptr,
                                                   bufA + OFF_X1, scale2,
                                                   nullptr, nullptr);
}

// round 13
// speedup vs baseline: 1.4867x; 1.4867x over previous
#include <cuda_runtime.h>
#include <cuda_bf16.h>
#include <cstdint>

// ---------------------------------------------------------------------------
// FuseBlock: B=2, C=128, H=W=256.  (b,c,h,w), HW=65536.
// Single-term bf16 mma.sync GEMMs; intermediates bf16; residuals fp32.
// attn: dwconv(q,k) + 8x8 circular conv fused, broadcast-friendly smem map.
// ---------------------------------------------------------------------------

#define EPSV   1e-6f

__device__ float g_bufA[100663296];   // bf16 views too
__device__ float g_bufB[100663296];
__device__ float g_misc[2097152];

#define OFF_M1   0
#define OFF_R1   131072
#define OFF_M2   262144
#define OFF_R2   393216
#define OFF_M3   524288
#define OFF_R3   655360
#define OFF_S1   786432
#define OFF_T1   787200
#define OFF_S2   787968
#define OFF_T2   788224
#define OFF_WBF  789504

// bf16-element offsets inside WBF region
#define WO_W1HI  0
#define WO_P1HI  98304
#define WO_W2HI  131072
#define WO_P2HI  163840

#define OFF_X1   50331648     // fp32 offset in bufA for x1 (after hidden)
#define ATT_OFF  33554432     // bf16 offset in bufB for attn (after v')
#define OFF_G16  50331648     // bf16 offset in bufB for g

// ---------------------------------------------------------------------------
__device__ __forceinline__ void mma16816(float* d, const uint32_t* a, const uint32_t* b) {
    asm volatile(
        "mma.sync.aligned.m16n8k16.row.col.f32.bf16.bf16.f32 "
        "{%0,%1,%2,%3}, {%4,%5,%6,%7}, {%8,%9}, {%0,%1,%2,%3};"
        : "+f"(d[0]), "+f"(d[1]), "+f"(d[2]), "+f"(d[3])
        : "r"(a[0]), "r"(a[1]), "r"(a[2]), "r"(a[3]), "r"(b[0]), "r"(b[1]));
}

__device__ __forceinline__ uint32_t pack_f2(float a, float b) {
    __nv_bfloat16 ha = __float2bfloat16(a);
    __nv_bfloat16 hb = __float2bfloat16(b);
    return (uint32_t)__bfloat16_as_ushort(ha) | ((uint32_t)__bfloat16_as_ushort(hb) << 16);
}
__device__ __forceinline__ float2 bf2_f2(uint32_t u) {
    float2 r;
    r.x = __uint_as_float(u << 16);
    r.y = __uint_as_float(u & 0xFFFF0000u);
    return r;
}

// ---------------------------------------------------------------------------
// mma GEMM (round-11 proven version).
// MODE 1: B fp32 planar; out bf16 = colRstd*(acc - colMean*rowS) + rowT
// MODE 2: B bf16 planar; out fp32 = Xres + acc*scaleRow
// MODE 3: B = v'*LN2(attn) (bf16, 256-ch layouts); out fp32; fused m3/r3 stats
// ---------------------------------------------------------------------------
#define BROW 136
#define GEMM_SMEM 36864

template <int MODE>
__global__ __launch_bounds__(256)
void mma_gemm(const __nv_bfloat16* __restrict__ Ahi, const void* __restrict__ Bv,
              void* __restrict__ Cv, int K, int CB, int CO, int mblocks,
              const float* __restrict__ colMean, const float* __restrict__ colRstd,
              const float* __restrict__ rowS, const float* __restrict__ rowT,
              const __nv_bfloat16* __restrict__ vbuf, const float* __restrict__ lnW,
              const float* __restrict__ lnB, const float* __restrict__ Xres,
              const float* __restrict__ scaleRow,
              float* __restrict__ m3out, float* __restrict__ r3out)
{
    extern __shared__ __align__(16) char smem[];
    uint32_t* BsHi = reinterpret_cast<uint32_t*>(smem);

    const int tid = threadIdx.x;
    const int wid = tid >> 5;
    const int lane = tid & 31;
    const int n0 = blockIdx.x * 128;
    const int bg = n0 >> 16;
    const int hw0 = n0 & 65535;
    const int warp_m = wid & 3;
    const int warp_n = wid >> 2;
    const int g  = lane >> 2;
    const int th = lane & 3;

    const int nchunks = K >> 7;

    for (int mb = 0; mb < mblocks; mb++) {
        const int m0 = mb * 128;

        float acc[2][8][4];
#pragma unroll
        for (int mt = 0; mt < 2; mt++)
#pragma unroll
            for (int nt = 0; nt < 8; nt++)
#pragma unroll
                for (int r = 0; r < 4; r++) acc[mt][nt][r] = 0.f;

        for (int ch = 0; ch < nchunks; ch++) {
            const int kc = ch << 7;

            if (mb == 0) {
                if (ch) __syncthreads();
#pragma unroll
                for (int it = 0; it < 8; it++) {
                    int idx = tid + it * 256;
                    int kp = idx >> 5;
                    int pg = (idx & 31) * 4;
                    int k0 = kc + kp * 2;
                    uint4 W;
                    if (MODE == 1) {
                        const float* Bf = (const float*)Bv;
                        float4 va = *reinterpret_cast<const float4*>(
                            Bf + (((size_t)(bg * CB + k0))     << 16) + hw0 + pg);
                        float4 vb = *reinterpret_cast<const float4*>(
                            Bf + (((size_t)(bg * CB + k0 + 1)) << 16) + hw0 + pg);
                        W.x = pack_f2(va.x, vb.x);
                        W.y = pack_f2(va.y, vb.y);
                        W.z = pack_f2(va.z, vb.z);
                        W.w = pack_f2(va.w, vb.w);
                    } else if (MODE == 2) {
                        const __nv_bfloat16* Bb = (const __nv_bfloat16*)Bv;
                        uint2 u = *reinterpret_cast<const uint2*>(
                            Bb + (((size_t)(bg * CB + k0))     << 16) + hw0 + pg);
                        uint2 v = *reinterpret_cast<const uint2*>(
                            Bb + (((size_t)(bg * CB + k0 + 1)) << 16) + hw0 + pg);
                        W.x = __byte_perm(u.x, v.x, 0x5410);
                        W.y = __byte_perm(u.x, v.x, 0x7632);
                        W.z = __byte_perm(u.y, v.y, 0x5410);
                        W.w = __byte_perm(u.y, v.y, 0x7632);
                    } else { // MODE 3
                        const __nv_bfloat16* Ab = (const __nv_bfloat16*)Bv;
                        uint2 ua0 = *reinterpret_cast<const uint2*>(
                            Ab + (((size_t)(bg * 256 + k0))     << 16) + hw0 + pg);
                        uint2 ua1 = *reinterpret_cast<const uint2*>(
                            Ab + (((size_t)(bg * 256 + k0 + 1)) << 16) + hw0 + pg);
                        uint2 uv0 = *reinterpret_cast<const uint2*>(
                            vbuf + (((size_t)(bg * 256 + k0))     << 16) + hw0 + pg);
                        uint2 uv1 = *reinterpret_cast<const uint2*>(
                            vbuf + (((size_t)(bg * 256 + k0 + 1)) << 16) + hw0 + pg);
                        float4 m4 = *reinterpret_cast<const float4*>(colMean + n0 + pg);
                        float4 r4 = *reinterpret_cast<const float4*>(colRstd + n0 + pg);
                        float wc0 = lnW[k0], bc0 = lnB[k0];
                        float wc1 = lnW[k0 + 1], bc1 = lnB[k0 + 1];
                        float2 a0 = bf2_f2(ua0.x), a1 = bf2_f2(ua0.y);
                        float2 c0 = bf2_f2(ua1.x), c1 = bf2_f2(ua1.y);
                        float2 v0 = bf2_f2(uv0.x), v1 = bf2_f2(uv0.y);
                        float2 w0 = bf2_f2(uv1.x), w1 = bf2_f2(uv1.y);
                        float r0a = v0.x * ((a0.x - m4.x) * r4.x * wc0 + bc0);
                        float r0b = v0.y * ((a0.y - m4.y) * r4.y * wc0 + bc0);
                        float r0c = v1.x * ((a1.x - m4.z) * r4.z * wc0 + bc0);
                        float r0d = v1.y * ((a1.y - m4.w) * r4.w * wc0 + bc0);
                        float r1a = w0.x * ((c0.x - m4.x) * r4.x * wc1 + bc1);
                        float r1b = w0.y * ((c0.y - m4.y) * r4.y * wc1 + bc1);
                        float r1c = w1.x * ((c1.x - m4.z) * r4.z * wc1 + bc1);
                        float r1d = w1.y * ((c1.y - m4.w) * r4.w * wc1 + bc1);
                        W.x = pack_f2(r0a, r1a);
                        W.y = pack_f2(r0b, r1b);
                        W.z = pack_f2(r0c, r1c);
                        W.w = pack_f2(r0d, r1d);
                    }
                    *reinterpret_cast<uint4*>(BsHi + kp * BROW + pg) = W;
                }
                __syncthreads();
            }

            // ---- 8 k-steps of 16 ----
#pragma unroll
            for (int ks = 0; ks < 8; ks++) {
                uint32_t ah[2][4];
#pragma unroll
                for (int mt = 0; mt < 2; mt++) {
                    int r = m0 + warp_m * 32 + mt * 16 + g;
                    size_t base = (size_t)r * K + kc + ks * 16 + th * 2;
                    ah[mt][0] = *reinterpret_cast<const uint32_t*>(Ahi + base);
                    ah[mt][1] = *reinterpret_cast<const uint32_t*>(Ahi + base + (size_t)8 * K);
                    ah[mt][2] = *reinterpret_cast<const uint32_t*>(Ahi + base + 8);
                    ah[mt][3] = *reinterpret_cast<const uint32_t*>(Ahi + base + (size_t)8 * K + 8);
                }
                const int kp0 = ks * 8 + th;
                const int kp1 = ks * 8 + 4 + th;
#pragma unroll
                for (int nt = 0; nt < 8; nt++) {
                    int n = warp_n * 64 + nt * 8 + g;
                    uint32_t bh[2];
                    bh[0] = BsHi[kp0 * BROW + n];
                    bh[1] = BsHi[kp1 * BROW + n];
#pragma unroll
                    for (int mt = 0; mt < 2; mt++)
                        mma16816(acc[mt][nt], ah[mt], bh);
                }
            }
        }

        // ---- epilogue ----
        float sEp[16], qEp[16];
        if (MODE == 3) {
#pragma unroll
            for (int i = 0; i < 16; i++) { sEp[i] = 0.f; qEp[i] = 0.f; }
        }
#pragma unroll
        for (int mt = 0; mt < 2; mt++) {
#pragma unroll
            for (int half = 0; half < 2; half++) {
                int o = m0 + warp_m * 32 + mt * 16 + g + half * 8;
                if (MODE == 1) {
                    float sv = rowS[o], tv = rowT[o];
                    __nv_bfloat16* Cb = (__nv_bfloat16*)Cv;
#pragma unroll
                    for (int nt = 0; nt < 8; nt++) {
                        int col = warp_n * 64 + nt * 8 + th * 2;
                        float2 cm = *reinterpret_cast<const float2*>(colMean + n0 + col);
                        float2 cr = *reinterpret_cast<const float2*>(colRstd + n0 + col);
                        float d0 = cr.x * (acc[mt][nt][half * 2 + 0] - cm.x * sv) + tv;
                        float d1 = cr.y * (acc[mt][nt][half * 2 + 1] - cm.y * sv) + tv;
                        *reinterpret_cast<uint32_t*>(
                            Cb + (((size_t)(bg * CO + o)) << 16) + hw0 + col) = pack_f2(d0, d1);
                    }
                } else {
                    float sc = scaleRow[o];
                    float* Cf = (float*)Cv;
#pragma unroll
                    for (int nt = 0; nt < 8; nt++) {
                        int col = warp_n * 64 + nt * 8 + th * 2;
                        size_t ix = (((size_t)(bg * CO + o)) << 16) + hw0 + col;
                        float2 xr = *reinterpret_cast<const float2*>(Xres + ix);
                        float2 ov;
                        ov.x = xr.x + acc[mt][nt][half * 2 + 0] * sc;
                        ov.y = xr.y + acc[mt][nt][half * 2 + 1] * sc;
                        *reinterpret_cast<float2*>(Cf + ix) = ov;
                        if (MODE == 3) {
                            sEp[nt * 2 + 0] += ov.x;
                            qEp[nt * 2 + 0] += ov.x * ov.x;
                            sEp[nt * 2 + 1] += ov.y;
                            qEp[nt * 2 + 1] += ov.y * ov.y;
                        }
                    }
                }
            }
        }

        if (MODE == 3) {
#pragma unroll
            for (int i = 0; i < 16; i++) {
#pragma unroll
                for (int off = 4; off <= 16; off <<= 1) {
                    sEp[i] += __shfl_xor_sync(0xFFFFFFFFu, sEp[i], off);
                    qEp[i] += __shfl_xor_sync(0xFFFFFFFFu, qEp[i], off);
                }
            }
            __syncthreads();
            float* sP = reinterpret_cast<float*>(smem);
            float* qP = sP + 512;
            if (lane < 4) {
#pragma unroll
                for (int nt = 0; nt < 8; nt++) {
#pragma unroll
                    for (int cc = 0; cc < 2; cc++) {
                        int col = warp_n * 64 + nt * 8 + lane * 2 + cc;
                        sP[warp_m * 128 + col] = sEp[nt * 2 + cc];
                        qP[warp_m * 128 + col] = qEp[nt * 2 + cc];
                    }
                }
            }
            __syncthreads();
            if (tid < 128) {
                float s = sP[tid] + sP[128 + tid] + sP[256 + tid] + sP[384 + tid];
                float q = qP[tid] + qP[128 + tid] + qP[256 + tid] + qP[384 + tid];
                float m = s * (1.f / 128.f);
                float var = q * (1.f / 128.f) - m * m;
                m3out[n0 + tid] = m;
                r3out[n0 + tid] = rsqrtf(var + EPSV);
            }
        }
    }
}

// ---------------------------------------------------------------------------
// per-pixel channel mean / rstd (fp32 input)
// ---------------------------------------------------------------------------
__global__ void stats_kernel(const float* __restrict__ in, float* __restrict__ mean,
                             float* __restrict__ rstd, int C) {
    int p = blockIdx.x * blockDim.x + threadIdx.x;
    int b = p >> 16, hw = p & 65535;
    const float* base = in + ((size_t)(b * C) << 16) + hw;
    float s = 0.f, ss = 0.f;
    for (int c = 0; c < C; c += 4) {
        float v0 = base[(size_t)(c + 0) << 16];
        float v1 = base[(size_t)(c + 1) << 16];
        float v2 = base[(size_t)(c + 2) << 16];
        float v3 = base[(size_t)(c + 3) << 16];
        s  += v0 + v1 + v2 + v3;
        ss += v0 * v0 + v1 * v1 + v2 * v2 + v3 * v3;
    }
    float invC = 1.f / (float)C;
    float m = s * invC;
    float var = ss * invC - m * m;
    mean[p] = m;
    rstd[p] = rsqrtf(var + EPSV);
}

// bf16-input variant (attn LN2 stats)
__global__ void stats_bf16_kernel(const __nv_bfloat16* __restrict__ in,
                                  float* __restrict__ mean, float* __restrict__ rstd, int C) {
    int p = blockIdx.x * blockDim.x + threadIdx.x;
    int b = p >> 16, hw = p & 65535;
    const __nv_bfloat16* base = in + ((size_t)(b * C) << 16) + hw;
    float s = 0.f, ss = 0.f;
    for (int c = 0; c < C; c += 4) {
        float v0 = __bfloat162float(base[(size_t)(c + 0) << 16]);
        float v1 = __bfloat162float(base[(size_t)(c + 1) << 16]);
        float v2 = __bfloat162float(base[(size_t)(c + 2) << 16]);
        float v3 = __bfloat162float(base[(size_t)(c + 3) << 16]);
        s  += v0 + v1 + v2 + v3;
        ss += v0 * v0 + v1 * v1 + v2 * v2 + v3 * v3;
    }
    float invC = 1.f / (float)C;
    float m = s * invC;
    float var = ss * invC - m * m;
    mean[p] = m;
    rstd[p] = rsqrtf(var + EPSV);
}

// ---------------------------------------------------------------------------
// One fold kernel for all 4 weight matrices. 1280 warp-rows.
// ---------------------------------------------------------------------------
__global__ void fold_all(const float* __restrict__ w_h1, const float* __restrict__ n1w,
                         const float* __restrict__ n1b,
                         const float* __restrict__ w_h2, const float* __restrict__ n3w,
                         const float* __restrict__ n3b, const float* __restrict__ b_h2,
                         const float* __restrict__ w_p1, const float* __restrict__ w_p2,
                         __nv_bfloat16* __restrict__ W1hi, __nv_bfloat16* __restrict__ W2hi,
                         __nv_bfloat16* __restrict__ P1hi, __nv_bfloat16* __restrict__ P2hi,
                         float* __restrict__ s1, float* __restrict__ t1,
                         float* __restrict__ s2, float* __restrict__ t2) {
    int r = blockIdx.x * 8 + (threadIdx.x >> 5);
    int lane = threadIdx.x & 31;
    if (r < 768) {
        float s = 0.f, t = 0.f;
        for (int c = lane; c < 128; c += 32) {
            float wv = w_h1[r * 128 + c];
            float wp = wv * n1w[c];
            W1hi[r * 128 + c] = __float2bfloat16(wp);
            s += wp;
            t += wv * n1b[c];
        }
#pragma unroll
        for (int off = 16; off; off >>= 1) {
            s += __shfl_xor_sync(0xFFFFFFFFu, s, off);
            t += __shfl_xor_sync(0xFFFFFFFFu, t, off);
        }
        if (lane == 0) { s1[r] = s; t1[r] = t; }
    } else if (r < 1024) {
        int o = r - 768;
        float s = 0.f, t = 0.f;
        for (int c = lane; c < 128; c += 32) {
            float wv = w_h2[o * 128 + c];
            float wp = wv * n3w[c];
            W2hi[o * 128 + c] = __float2bfloat16(wp);
            s += wp;
            t += wv * n3b[c];
        }
#pragma unroll
        for (int off = 16; off; off >>= 1) {
            s += __shfl_xor_sync(0xFFFFFFFFu, s, off);
            t += __shfl_xor_sync(0xFFFFFFFFu, t, off);
        }
        if (lane == 0) { s2[o] = s; t2[o] = t + b_h2[o]; }
    } else if (r < 1152) {
        int o = r - 1024;
        for (int c = lane; c < 256; c += 32)
            P1hi[o * 256 + c] = __float2bfloat16(w_p1[o * 256 + c]);
    } else {
        int o = r - 1152;
        for (int c = lane; c < 128; c += 32)
            P2hi[o * 128 + c] = __float2bfloat16(w_p2[o * 128 + c]);
    }
}

// ---------------------------------------------------------------------------
// v-only depthwise 3x3: hidden ch 512..767 -> v' (256-ch layout)
// ---------------------------------------------------------------------------
__global__ __launch_bounds__(256)
void dwconv_v(const __nv_bfloat16* __restrict__ hidden, const float* __restrict__ w,
              __nv_bfloat16* __restrict__ vout) {
    int z = blockIdx.y;
    int b = z >> 8, c = z & 255;
    int h0 = blockIdx.x * 8;
    __shared__ float tile[10][258];
    const __nv_bfloat16* base = hidden + ((size_t)(b * 768 + 512 + c) << 16);
    int tid = threadIdx.x;
#pragma unroll
    for (int r = 0; r < 10; r++) {
        int gh = h0 - 1 + r;
        tile[r][tid + 1] = (gh >= 0 && gh < 256) ? __bfloat162float(base[gh * 256 + tid]) : 0.f;
    }
    if (tid < 10) { tile[tid][0] = 0.f; tile[tid][257] = 0.f; }
    __syncthreads();
    const float* wc = w + (size_t)(512 + c) * 9;
    float w0 = wc[0], w1 = wc[1], w2 = wc[2], w3 = wc[3], w4 = wc[4],
          w5 = wc[5], w6 = wc[6], w7 = wc[7], w8 = wc[8];
    __nv_bfloat16* obase = vout + ((size_t)(b * 256 + c) << 16) + h0 * 256 + tid;
#pragma unroll
    for (int y = 0; y < 8; y++) {
        float s = w0 * tile[y][tid]     + w1 * tile[y][tid + 1]     + w2 * tile[y][tid + 2]
                + w3 * tile[y + 1][tid] + w4 * tile[y + 1][tid + 1] + w5 * tile[y + 1][tid + 2]
                + w6 * tile[y + 2][tid] + w7 * tile[y + 2][tid + 1] + w8 * tile[y + 2][tid + 2];
        obase[y * 256] = __float2bfloat16(s);
    }
}

// ---------------------------------------------------------------------------
// Fused dwconv(q), dwconv(k) + 8x8 circular conv.  Broadcast-friendly map:
// circ phase thread = (patch p = tid>>3, row i = tid&7); q-reads broadcast
// across the 8 lanes of a subgroup; qs2/ks2 row stride 72 words.
// grid (32 strips, B*256 channels)
// ---------------------------------------------------------------------------
__global__ __launch_bounds__(256)
void attn_fused(const __nv_bfloat16* __restrict__ hidden, const float* __restrict__ wdw,
                __nv_bfloat16* __restrict__ attn) {
    int z = blockIdx.y;
    int b = z >> 8, c = z & 255;
    int h0 = blockIdx.x * 8;
    __shared__ float tq[10][258];
    __shared__ float tk[10][258];
    __shared__ float qs2[32][72];   // [patch][i*8+j], stride 72
    __shared__ float ks2[32][72];

    const __nv_bfloat16* qb = hidden + ((size_t)(b * 768 + c)       << 16);
    const __nv_bfloat16* kb = hidden + ((size_t)(b * 768 + 256 + c) << 16);
    int tid = threadIdx.x;
#pragma unroll
    for (int r = 0; r < 10; r++) {
        int gh = h0 - 1 + r;
        bool ok = (gh >= 0 && gh < 256);
        tq[r][tid + 1] = ok ? __bfloat162float(qb[gh * 256 + tid]) : 0.f;
        tk[r][tid + 1] = ok ? __bfloat162float(kb[gh * 256 + tid]) : 0.f;
    }
    if (tid < 10) {
        tq[tid][0] = 0.f; tq[tid][257] = 0.f;
        tk[tid][0] = 0.f; tk[tid][257] = 0.f;
    }
    __syncthreads();

    {
        const float* wq = wdw + (size_t)c * 9;
        const float* wk = wdw + (size_t)(256 + c) * 9;
        float q0 = wq[0], q1 = wq[1], q2 = wq[2], q3 = wq[3], q4 = wq[4],
              q5 = wq[5], q6 = wq[6], q7 = wq[7], q8 = wq[8];
        float k0 = wk[0], k1 = wk[1], k2 = wk[2], k3 = wk[3], k4 = wk[4],
              k5 = wk[5], k6 = wk[6], k7 = wk[7], k8 = wk[8];
        int p = tid >> 3, jj = tid & 7;   // column tid -> patch p, in-patch col jj
#pragma unroll
        for (int y = 0; y < 8; y++) {
            float qv = q0 * tq[y][tid]     + q1 * tq[y][tid + 1]     + q2 * tq[y][tid + 2]
                     + q3 * tq[y + 1][tid] + q4 * tq[y + 1][tid + 1] + q5 * tq[y + 1][tid + 2]
                     + q6 * tq[y + 2][tid] + q7 * tq[y + 2][tid + 1] + q8 * tq[y + 2][tid + 2];
            float kv = k0 * tk[y][tid]     + k1 * tk[y][tid + 1]     + k2 * tk[y][tid + 2]
                     + k3 * tk[y + 1][tid] + k4 * tk[y + 1][tid + 1] + k5 * tk[y + 1][tid + 2]
                     + k6 * tk[y + 2][tid] + k7 * tk[y + 2][tid + 1] + k8 * tk[y + 2][tid + 2];
            qs2[p][y * 8 + jj] = qv;     // banks: 8*(lane>>3)+(lane&7) -> 32 distinct
            ks2[p][y * 8 + jj] = kv;
        }
    }
    __syncthreads();

    // circ conv: p = tid>>3 (patch), i = tid&7 (output row)
    int p = tid >> 3, i = tid & 7;
    float acc[8];
#pragma unroll
    for (int j = 0; j < 8; j++) acc[j] = 0.f;
#pragma unroll
    for (int a = 0; a < 8; a++) {
        int ra = (i - a) & 7;
        float qr[8], kr[8];
        *reinterpret_cast<float4*>(&qr[0]) = *reinterpret_cast<const float4*>(&qs2[p][a * 8]);      // broadcast x8
        *reinterpret_cast<float4*>(&qr[4]) = *reinterpret_cast<const float4*>(&qs2[p][a * 8 + 4]);
        *reinterpret_cast<float4*>(&kr[0]) = *reinterpret_cast<const float4*>(&ks2[p][ra * 8]);
        *reinterpret_cast<float4*>(&kr[4]) = *reinterpret_cast<const float4*>(&ks2[p][ra * 8 + 4]);
#pragma unroll
        for (int bq = 0; bq < 8; bq++)
#pragma unroll
            for (int j = 0; j < 8; j++)
                acc[j] += qr[bq] * kr[(j - bq) & 7];
    }

    uint4 ov;
    ov.x = pack_f2(acc[0], acc[1]);
    ov.y = pack_f2(acc[2], acc[3]);
    ov.z = pack_f2(acc[4], acc[5]);
    ov.w = pack_f2(acc[6], acc[7]);
    *reinterpret_cast<uint4*>(attn + ((size_t)(b * 256 + c) << 16)
                              + (h0 + i) * 256 + p * 8) = ov;
}

// ---------------------------------------------------------------------------
// FFN gate: dw3x3 on ch c and c+128 of h, multiply. grid (32, B*128)
// ---------------------------------------------------------------------------
__global__ __launch_bounds__(256)
void gate_kernel(const __nv_bfloat16* __restrict__ h, const float* __restrict__ wdw,
                 __nv_bfloat16* __restrict__ g) {
    int z = blockIdx.y;
    int b = z >> 7, c = z & 127;
    int h0 = blockIdx.x * 8;
    __shared__ float t1s[10][258];
    __shared__ float t2s[10][258];
    const __nv_bfloat16* base1 = h + ((size_t)(b * 256 + c) << 16);
    const __nv_bfloat16* base2 = h + ((size_t)(b * 256 + c + 128) << 16);
    int tid = threadIdx.x;
#pragma unroll
    for (int r = 0; r < 10; r++) {
        int gh = h0 - 1 + r;
        bool ok = (gh >= 0 && gh < 256);
        t1s[r][tid + 1] = ok ? __bfloat162float(base1[gh * 256 + tid]) : 0.f;
        t2s[r][tid + 1] = ok ? __bfloat162float(base2[gh * 256 + tid]) : 0.f;
    }
    if (tid < 10) {
        t1s[tid][0] = 0.f; t1s[tid][257] = 0.f;
        t2s[tid][0] = 0.f; t2s[tid][257] = 0.f;
    }
    __syncthreads();
    const float* wa = wdw + (size_t)c * 9;
    const float* wb = wdw + (size_t)(c + 128) * 9;
    float a0 = wa[0], a1 = wa[1], a2 = wa[2], a3 = wa[3], a4 = wa[4],
          a5 = wa[5], a6 = wa[6], a7 = wa[7], a8 = wa[8];
    float b0 = wb[0], b1 = wb[1], b2 = wb[2], b3 = wb[3], b4 = wb[4],
          b5 = wb[5], b6 = wb[6], b7 = wb[7], b8 = wb[8];
    __nv_bfloat16* obase = g + ((size_t)(b * 128 + c) << 16) + h0 * 256 + tid;
#pragma unroll
    for (int y = 0; y < 8; y++) {
        float s1 = a0 * t1s[y][tid]     + a1 * t1s[y][tid + 1]     + a2 * t1s[y][tid + 2]
                 + a3 * t1s[y + 1][tid] + a4 * t1s[y + 1][tid + 1] + a5 * t1s[y + 1][tid + 2]
                 + a6 * t1s[y + 2][tid] + a7 * t1s[y + 2][tid + 1] + a8 * t1s[y + 2][tid + 2];
        float s2 = b0 * t2s[y][tid]     + b1 * t2s[y][tid + 1]     + b2 * t2s[y][tid + 2]
                 + b3 * t2s[y + 1][tid] + b4 * t2s[y + 1][tid + 1] + b5 * t2s[y + 1][tid + 2]
                 + b6 * t2s[y + 2][tid] + b7 * t2s[y + 2][tid + 1] + b8 * t2s[y + 2][tid + 2];
        obase[y * 256] = __float2bfloat16(s1 * s2);
    }
}

// ---------------------------------------------------------------------------
extern "C" void kernel_launch(void* const* d_in, const int* in_sizes, int n_in,
                              void* d_out, int out_size) {
    const float* x      = (const float*)d_in[0];
    const float* n1w    = (const float*)d_in[1];
    const float* n1b    = (const float*)d_in[2];
    const float* w_h1   = (const float*)d_in[3];
    const float* w_dw1  = (const float*)d_in[4];
    const float* n2w    = (const float*)d_in[5];
    const float* n2b    = (const float*)d_in[6];
    const float* w_p1   = (const float*)d_in[7];
    const float* n3w    = (const float*)d_in[8];
    const float* n3b    = (const float*)d_in[9];
    const float* w_h2   = (const float*)d_in[10];
    const float* b_h2   = (const float*)d_in[11];
    const float* w_dw2  = (const float*)d_in[12];
    const float* w_p2   = (const float*)d_in[13];
    const float* scale1 = (const float*)d_in[14];
    const float* scale2 = (const float*)d_in[15];
    float* out = (float*)d_out;

    float *bufA, *bufB, *misc;
    cudaGetSymbolAddress((void**)&bufA, g_bufA);
    cudaGetSymbolAddress((void**)&bufB, g_bufB);
    cudaGetSymbolAddress((void**)&misc, g_misc);

    __nv_bfloat16* bA16 = reinterpret_cast<__nv_bfloat16*>(bufA);
    __nv_bfloat16* bB16 = reinterpret_cast<__nv_bfloat16*>(bufB);

    float* m1 = misc + OFF_M1;
    float* r1 = misc + OFF_R1;
    float* m2 = misc + OFF_M2;
    float* r2 = misc + OFF_R2;
    float* m3 = misc + OFF_M3;
    float* r3 = misc + OFF_R3;
    float* s1 = misc + OFF_S1;
    float* t1 = misc + OFF_T1;
    float* s2 = misc + OFF_S2;
    float* t2 = misc + OFF_T2;
    __nv_bfloat16* wbf = reinterpret_cast<__nv_bfloat16*>(misc + OFF_WBF);
    __nv_bfloat16* W1hi = wbf + WO_W1HI;
    __nv_bfloat16* P1hi = wbf + WO_P1HI;
    __nv_bfloat16* W2hi = wbf + WO_W2HI;
    __nv_bfloat16* P2hi = wbf + WO_P2HI;

    cudaFuncSetAttribute(mma_gemm<1>, cudaFuncAttributeMaxDynamicSharedMemorySize, GEMM_SMEM);
    cudaFuncSetAttribute(mma_gemm<2>, cudaFuncAttributeMaxDynamicSharedMemorySize, GEMM_SMEM);
    cudaFuncSetAttribute(mma_gemm<3>, cudaFuncAttributeMaxDynamicSharedMemorySize, GEMM_SMEM);

    // folds + LN1 stats
    fold_all<<<160, 256>>>(w_h1, n1w, n1b, w_h2, n3w, n3b, b_h2, w_p1, w_p2,
                           W1hi, W2hi, P1hi, P2hi, s1, t1, s2, t2);
    stats_kernel<<<512, 256>>>(x, m1, r1, 128);

    // K1: hidden(bf16, 768ch in bufA) = LN1-folded conv1x1(x)
    mma_gemm<1><<<dim3(1024, 1), 256, GEMM_SMEM>>>(W1hi, x, bA16, 128, 128, 768, 6,
                                                   m1, r1, s1, t1,
                                                   nullptr, nullptr, nullptr, nullptr, nullptr,
                                                   nullptr, nullptr);
    // v' = dwconv(hidden[512:768]) -> bufB (256-ch layout)
    dwconv_v<<<dim3(32, 512), 256>>>(bA16, w_dw1, bB16);

    // attn = circconv8(dwconv(q), dwconv(k)) -> bufB + ATT_OFF
    attn_fused<<<dim3(32, 512), 256>>>(bA16, w_dw1, bB16 + ATT_OFF);
    stats_bf16_kernel<<<512, 256>>>(bB16 + ATT_OFF, m2, r2, 256);

    // K3b: x1(fp32) = x + scale1 * ( w_p1 @ (v' * LN2(attn)) ); fused stats -> m3,r3
    mma_gemm<3><<<dim3(1024, 1), 256, GEMM_SMEM>>>(P1hi, bB16 + ATT_OFF, bufA + OFF_X1,
                                                   256, 256, 128, 1,
                                                   m2, r2, nullptr, nullptr,
                                                   bB16, n2w, n2b, x, scale1,
                                                   m3, r3);

    // K4: h(bf16, 256ch in bufB) = LN3-folded conv1x1(x1) + b_h2
    mma_gemm<1><<<dim3(1024, 1), 256, GEMM_SMEM>>>(W2hi, bufA + OFF_X1, bB16, 128, 128, 256, 2,
                                                   m3, r3, s2, t2,
                                                   nullptr, nullptr, nullptr, nullptr, nullptr,
                                                   nullptr, nullptr);
    // gate
    gate_kernel<<<dim3(32, 256), 256>>>(bB16, w_dw2, bB16 + OFF_G16);
    // K5b: out = x1 + scale2 * (w_p2 @ g)
    mma_gemm<2><<<dim3(1024, 1), 256, GEMM_SMEM>>>(P2hi, bB16 + OFF_G16, out, 128, 128, 128, 1,
                                                   nullptr, nullptr, nullptr, nullptr,
                                                   nullptr, nullptr, nullptr,
                                                   bufA + OFF_X1, scale2,
                                                   nullptr, nullptr);
}